// round 1
// baseline (speedup 1.0000x reference)
#include <cuda_runtime.h>
#include <math.h>

#define NBINS 256
#define HW    (224 * 224)   // 50176
#define NB    8             // batch
#define EPSF  1e-10f

// Scratch (allocation-free: __device__ globals)
__device__ float g_joint[NB * NBINS * NBINS];  // 2 MB
__device__ float g_m1[NB * NBINS];
__device__ float g_m2[NB * NBINS];

// ---------------------------------------------------------------------------
// K0: zero scratch
// ---------------------------------------------------------------------------
__global__ void mi_zero_kernel() {
    int idx = blockIdx.x * blockDim.x + threadIdx.x;
    int stride = gridDim.x * blockDim.x;
    const int total = NB * NBINS * NBINS;
    for (int i = idx; i < total; i += stride) g_joint[i] = 0.0f;
    if (idx < NB * NBINS) { g_m1[idx] = 0.0f; g_m2[idx] = 0.0f; }
}

// ---------------------------------------------------------------------------
// K1: per-pixel sparse Parzen accumulation.
// Each pixel value x contributes exp(-50*(x - bin)^2) to at most 3 bins
// (terms beyond |d|=1.5 underflow to exactly 0 in fp32, matching reference).
// Marginals accumulate in smem per CTA; joint via global fp32 atomics.
// Grid: (HW/256, NB), block 256.
// ---------------------------------------------------------------------------
__global__ void mi_accum_kernel(const float* __restrict__ in1,
                                const float* __restrict__ in2) {
    __shared__ float s_m1[NBINS];
    __shared__ float s_m2[NBINS];

    const int b = blockIdx.y;
    const int t = threadIdx.x;

    s_m1[t] = 0.0f;
    s_m2[t] = 0.0f;
    __syncthreads();

    const int pix = blockIdx.x * blockDim.x + t;
    const float x1 = in1[b * HW + pix] * 255.0f;
    const float x2 = in2[b * HW + pix] * 255.0f;

    const int i0 = __float2int_rn(x1);
    const int j0 = __float2int_rn(x2);

    float w1[3], w2[3];
#pragma unroll
    for (int a = 0; a < 3; a++) {
        float d1 = x1 - (float)(i0 + a - 1);
        float d2 = x2 - (float)(j0 + a - 1);
        w1[a] = __expf(-50.0f * d1 * d1);
        w2[a] = __expf(-50.0f * d2 * d2);
    }
    // Out-of-range bins (only possible at the boundaries)
    if (i0 == 0)           w1[0] = 0.0f;
    if (i0 == NBINS - 1)   w1[2] = 0.0f;
    if (j0 == 0)           w2[0] = 0.0f;
    if (j0 == NBINS - 1)   w2[2] = 0.0f;

    // Marginals in shared memory (skip exact zeros: ~1.76 adds/value)
#pragma unroll
    for (int a = 0; a < 3; a++) {
        if (w1[a] != 0.0f) atomicAdd(&s_m1[i0 + a - 1], w1[a]);
        if (w2[a] != 0.0f) atomicAdd(&s_m2[j0 + a - 1], w2[a]);
    }

    // Joint: up to 9 scatter adds, typically ~3 survive underflow
    float* joint = g_joint + (size_t)b * NBINS * NBINS;
#pragma unroll
    for (int a = 0; a < 3; a++) {
        if (w1[a] == 0.0f) continue;
        const int row = (i0 + a - 1) * NBINS;
#pragma unroll
        for (int c = 0; c < 3; c++) {
            float w = w1[a] * w2[c];
            if (w != 0.0f) atomicAdd(&joint[row + (j0 + c - 1)], w);
        }
    }

    __syncthreads();
    // One global atomic per bin per CTA
    if (s_m1[t] != 0.0f) atomicAdd(&g_m1[b * NBINS + t], s_m1[t]);
    if (s_m2[t] != 0.0f) atomicAdd(&g_m2[b * NBINS + t], s_m2[t]);
}

// ---------------------------------------------------------------------------
// K2: per-batch entropies + MI. One CTA (256 threads) per batch.
// ---------------------------------------------------------------------------
__device__ __forceinline__ float block_reduce_sum_256(float val, float* sh8) {
    __syncthreads();   // protect sh8 reuse across calls
#pragma unroll
    for (int ofs = 16; ofs >= 1; ofs >>= 1)
        val += __shfl_xor_sync(0xffffffffu, val, ofs);
    const int warp = threadIdx.x >> 5;
    if ((threadIdx.x & 31) == 0) sh8[warp] = val;
    __syncthreads();
    float total = 0.0f;
#pragma unroll
    for (int i = 0; i < 8; i++) total += sh8[i];
    return total;
}

__global__ void mi_reduce_kernel(float* __restrict__ out) {
    __shared__ float sh8[8];
    const int b = blockIdx.x;
    const int t = threadIdx.x;
    const float invHW = 1.0f / (float)HW;

    // --- marginal 1 ---
    float q1 = g_m1[b * NBINS + t] * invHW;            // pdf before normalization
    float S1 = block_reduce_sum_256(q1, sh8) + EPSF;   // normalization
    float p1 = q1 / S1;
    float H1 = -block_reduce_sum_256(p1 * log2f(p1 + EPSF), sh8);

    // --- marginal 2 ---
    float q2 = g_m2[b * NBINS + t] * invHW;
    float S2 = block_reduce_sum_256(q2, sh8) + EPSF;
    float p2 = q2 / S2;
    float H2 = -block_reduce_sum_256(p2 * log2f(p2 + EPSF), sh8);

    // --- joint ---
    const float* joint = g_joint + (size_t)b * NBINS * NBINS;
    float s = 0.0f;
    for (int i = t; i < NBINS * NBINS; i += 256) s += joint[i];
    float Sj = block_reduce_sum_256(s, sh8) + EPSF;
    float invSj = 1.0f / Sj;

    float hs = 0.0f;
    for (int i = t; i < NBINS * NBINS; i += 256) {
        float p = joint[i] * invSj;
        hs += p * log2f(p + EPSF);
    }
    float Hj = -block_reduce_sum_256(hs, sh8);

    if (t == 0) {
        float mi = H1 + H2 - Hj;
        out[b] = 2.0f * mi / (H1 + H2);   // NORMALIZE = True
    }
}

// ---------------------------------------------------------------------------
extern "C" void kernel_launch(void* const* d_in, const int* in_sizes, int n_in,
                              void* d_out, int out_size) {
    const float* in1 = (const float*)d_in[0];
    const float* in2 = (const float*)d_in[1];
    // d_in[2] = bins: exactly 0..255, folded into the kernels analytically.
    float* out = (float*)d_out;

    mi_zero_kernel<<<512, 256>>>();
    dim3 grid(HW / 256, NB);
    mi_accum_kernel<<<grid, 256>>>(in1, in2);
    mi_reduce_kernel<<<NB, 256>>>(out);
}

// round 2
// speedup vs baseline: 3.7397x; 3.7397x over previous
#include <cuda_runtime.h>
#include <math.h>

#define NBINS 256
#define HW    50176          // 224*224
#define NB    8
#define EPSF  1e-10f
#define WCUT  1e-12f         // skip atomics below this; error << fp32 noise

// Scratch (__device__ globals are zero-initialized at module load; kernels
// below restore them to zero after use, so every graph replay sees zeros).
__device__ float g_joint[NB * NBINS * NBINS];   // 2 MB
__device__ float g_m1[NB * NBINS];
__device__ float g_m2[NB * NBINS];
__device__ float g_s1[NB], g_s2[NB], g_sj[NB];  // analytic normalizers
__device__ float g_hj[NB];                      // joint entropy partials (atomic)
__device__ float g_h1[NB], g_h2[NB];            // marginal entropy (plain store)

// ---------------------------------------------------------------------------
__device__ __forceinline__ float blk_sum_256(float v, float* s8) {
    __syncthreads();                 // protect s8 reuse across calls
#pragma unroll
    for (int o = 16; o >= 1; o >>= 1) v += __shfl_xor_sync(0xffffffffu, v, o);
    if ((threadIdx.x & 31) == 0) s8[threadIdx.x >> 5] = v;
    __syncthreads();
    float r = 0.0f;
#pragma unroll
    for (int i = 0; i < 8; i++) r += s8[i];
    return r;
}

// Only bins floor(x) and floor(x)+1 carry non-negligible weight (3rd-nearest
// bin weight <= exp(-50) ~ 2e-22). Both weights from 2 MUFU ops via
// exp(-50(1-f)^2) = exp(-50 f^2) * exp(100 f - 50).
__device__ __forceinline__ void weights(float x, int& i0, float& wa, float& wb) {
    i0 = __float2int_rd(x);
    i0 = min(max(i0, 0), NBINS - 2);
    float f = x - (float)i0;
    wa = __expf(-50.0f * f * f);
    wb = wa * __expf(100.0f * f - 50.0f);
}

// ---------------------------------------------------------------------------
// K1: sparse Parzen accumulation. 4 pixels/thread via float4.
// Grid (49, NB), block 256.  Also computes analytic normalizers S1,S2,Sj.
// ---------------------------------------------------------------------------
__global__ void __launch_bounds__(256) mi_accum(const float4* __restrict__ in1,
                                                const float4* __restrict__ in2) {
    __shared__ float s_m1[NBINS];
    __shared__ float s_m2[NBINS];
    __shared__ float s8[8];

    const int b = blockIdx.y;
    const int t = threadIdx.x;
    s_m1[t] = 0.0f;
    s_m2[t] = 0.0f;
    __syncthreads();

    const int idx = blockIdx.x * 256 + t;            // float4 index in image
    const float4 v1 = in1[b * (HW / 4) + idx];
    const float4 v2 = in2[b * (HW / 4) + idx];

    float* __restrict__ joint = g_joint + (size_t)b * NBINS * NBINS;
    float sw1 = 0.0f, sw2 = 0.0f, swj = 0.0f;

    const float* p1v = (const float*)&v1;
    const float* p2v = (const float*)&v2;
#pragma unroll
    for (int k = 0; k < 4; k++) {
        float x1 = p1v[k] * 255.0f;
        float x2 = p2v[k] * 255.0f;
        int i0, j0;
        float w1a, w1b, w2a, w2b;
        weights(x1, i0, w1a, w1b);
        weights(x2, j0, w2a, w2b);

        float t1 = w1a + w1b, t2 = w2a + w2b;
        sw1 += t1; sw2 += t2; swj += t1 * t2;

        if (w1a > WCUT) atomicAdd(&s_m1[i0],     w1a);
        if (w1b > WCUT) atomicAdd(&s_m1[i0 + 1], w1b);
        if (w2a > WCUT) atomicAdd(&s_m2[j0],     w2a);
        if (w2b > WCUT) atomicAdd(&s_m2[j0 + 1], w2b);

        float p;
        p = w1a * w2a; if (p > WCUT) atomicAdd(&joint[i0 * NBINS + j0],           p);
        p = w1a * w2b; if (p > WCUT) atomicAdd(&joint[i0 * NBINS + j0 + 1],       p);
        p = w1b * w2a; if (p > WCUT) atomicAdd(&joint[(i0 + 1) * NBINS + j0],     p);
        p = w1b * w2b; if (p > WCUT) atomicAdd(&joint[(i0 + 1) * NBINS + j0 + 1], p);
    }

    float S1 = blk_sum_256(sw1, s8);
    float S2 = blk_sum_256(sw2, s8);
    float SJ = blk_sum_256(swj, s8);
    if (t == 0) {
        atomicAdd(&g_s1[b], S1);
        atomicAdd(&g_s2[b], S2);
        atomicAdd(&g_sj[b], SJ);
    }

    // flush marginal histograms (one global atomic per bin per CTA)
    if (s_m1[t] != 0.0f) atomicAdd(&g_m1[b * NBINS + t], s_m1[t]);
    if (s_m2[t] != 0.0f) atomicAdd(&g_m2[b * NBINS + t], s_m2[t]);
}

// ---------------------------------------------------------------------------
// K2: entropies. Grid (16, NB), block 256. Each CTA: 4096 joint entries
// (single pass, MUFU log2), zeroes them afterward. CTA x==0 also does both
// marginals and zeroes g_m1/g_m2.
// ---------------------------------------------------------------------------
__global__ void __launch_bounds__(256) mi_entropy() {
    __shared__ float s8[8];
    const int b = blockIdx.y;
    const int cx = blockIdx.x;
    const int t = threadIdx.x;

    const float invSj = 1.0f / (g_sj[b] + EPSF);
    float4* __restrict__ j4 =
        (float4*)(g_joint + (size_t)b * NBINS * NBINS) + cx * 1024;

    float hj = 0.0f;
#pragma unroll
    for (int k = 0; k < 4; k++) {
        float4 v = j4[k * 256 + t];
        float p0 = v.x * invSj, p1 = v.y * invSj;
        float p2 = v.z * invSj, p3 = v.w * invSj;
        hj += p0 * __log2f(p0 + EPSF) + p1 * __log2f(p1 + EPSF)
            + p2 * __log2f(p2 + EPSF) + p3 * __log2f(p3 + EPSF);
        j4[k * 256 + t] = make_float4(0.0f, 0.0f, 0.0f, 0.0f);  // re-zero
    }
    float HJ = blk_sum_256(hj, s8);
    if (t == 0) atomicAdd(&g_hj[b], HJ);

    if (cx == 0) {
        const float invHW = 1.0f / (float)HW;
        // marginal 1
        float q1 = g_m1[b * NBINS + t] * invHW;
        float n1 = g_s1[b] * invHW + EPSF;
        float pm1 = q1 / n1;
        float H1 = blk_sum_256(pm1 * __log2f(pm1 + EPSF), s8);
        // marginal 2
        float q2 = g_m2[b * NBINS + t] * invHW;
        float n2 = g_s2[b] * invHW + EPSF;
        float pm2 = q2 / n2;
        float H2 = blk_sum_256(pm2 * __log2f(pm2 + EPSF), s8);
        if (t == 0) { g_h1[b] = H1; g_h2[b] = H2; }   // plain store, no zeroing needed
        g_m1[b * NBINS + t] = 0.0f;                    // re-zero for next replay
        g_m2[b * NBINS + t] = 0.0f;
    }
}

// ---------------------------------------------------------------------------
// K3: final MI + restore atomic scratch to zero.
// ---------------------------------------------------------------------------
__global__ void mi_final(float* __restrict__ out) {
    int b = threadIdx.x;
    if (b < NB) {
        float H1 = -g_h1[b], H2 = -g_h2[b], HJ = -g_hj[b];
        float mi = H1 + H2 - HJ;
        out[b] = 2.0f * mi / (H1 + H2);   // NORMALIZE = True
        g_hj[b] = 0.0f;
        g_s1[b] = 0.0f; g_s2[b] = 0.0f; g_sj[b] = 0.0f;
    }
}

// ---------------------------------------------------------------------------
extern "C" void kernel_launch(void* const* d_in, const int* in_sizes, int n_in,
                              void* d_out, int out_size) {
    const float4* in1 = (const float4*)d_in[0];
    const float4* in2 = (const float4*)d_in[1];
    // d_in[2] = bins (exactly 0..255) folded in analytically.
    float* out = (float*)d_out;

    mi_accum<<<dim3(49, NB), 256>>>(in1, in2);
    mi_entropy<<<dim3(16, NB), 256>>>();
    mi_final<<<1, 32>>>(out);
}